// round 1
// baseline (speedup 1.0000x reference)
#include <cuda_runtime.h>
#include <cstdint>

// ============================================================
// VectorQuantizer: idx = argmin_k ||z - c_k||^2 ; z_q = c[idx];
// loss = (1 + 0.25) * mean((z_q - z_e)^2)   (both loss terms equal in value)
// ============================================================

#define DDIM 256
#define MAXN 32768
#define MAXK 8192

__device__ float g_cnorm[MAXK];
__device__ int   g_idx[MAXN];
__device__ float g_part[MAXN];

// ---------------- codebook row norms ----------------
__global__ void k_cnorm(const float* __restrict__ cb, int K) {
    int warp = blockIdx.x * (blockDim.x >> 5) + (threadIdx.x >> 5);
    int lane = threadIdx.x & 31;
    if (warp >= K) return;
    const float4* row = (const float4*)(cb + (long)warp * DDIM);
    float s = 0.f;
#pragma unroll
    for (int i = 0; i < 2; i++) {
        float4 v = row[lane + 32 * i];
        s += v.x * v.x + v.y * v.y + v.z * v.z + v.w * v.w;
    }
#pragma unroll
    for (int o = 16; o; o >>= 1) s += __shfl_xor_sync(0xffffffffu, s, o);
    if (lane == 0) g_cnorm[warp] = s;
}

// ---------------- fused GEMM + argmin ----------------
// block tile: 128 tokens x 128 codes, 256 threads, 8x8 per thread.
// A (tokens) fully resident in smem; B (codes) streamed in 64-d chunks.
#define TM 128
#define TC 128
#define DCH 64
#define A_STRIDE4 65   // (256 + 4 pad) / 4 floats -> conflict-free LDS.128
#define B_STRIDE4 17   // (64 + 4 pad) / 4
#define SMEM_A4 (TM * A_STRIDE4)   // 8320 float4
#define SMEM_B4 (TC * B_STRIDE4)   // 2176 float4
#define SMEM_BYTES ((SMEM_A4 + SMEM_B4) * 16)   // 167936 B

__device__ __forceinline__ unsigned fkey(float f) {
    // monotonic uint encoding of float (handles negatives)
    unsigned u = __float_as_uint(f);
    return (u & 0x80000000u) ? ~u : (u | 0x80000000u);
}

__global__ void __launch_bounds__(256, 1)
k_argmin(const float* __restrict__ z, const float* __restrict__ cb, int K) {
    extern __shared__ float4 sm4[];
    float4* As4 = sm4;
    float4* Bs4 = sm4 + SMEM_A4;
    int tid = threadIdx.x;
    int tx = tid & 15;       // code group (16)
    int ty = tid >> 4;       // token group (16)
    long t0 = (long)blockIdx.x * TM;

    // load full A panel: 128 tokens x 256 d (coalesced, conflict-free STS)
#pragma unroll
    for (int it = 0; it < (TM * (DDIM / 4)) / 256; it++) {  // 32 iters
        int f = tid + it * 256;
        int t = f >> 6, d4 = f & 63;
        As4[t * A_STRIDE4 + d4] = ((const float4*)z)[(t0 + t) * (DDIM / 4) + d4];
    }

    float rmin[8];
    int ridx[8];
#pragma unroll
    for (int i = 0; i < 8; i++) { rmin[i] = 3.4e38f; ridx[i] = 0; }

    int ntiles = K / TC;
    for (int kt = 0; kt < ntiles; kt++) {
        float acc[8][8];
#pragma unroll
        for (int i = 0; i < 8; i++)
#pragma unroll
            for (int j = 0; j < 8; j++) acc[i][j] = 0.f;

        for (int dc = 0; dc < DDIM; dc += DCH) {
            __syncthreads();   // protect previous B chunk readers (and A on iter 0)
#pragma unroll
            for (int it = 0; it < (TC * (DCH / 4)) / 256; it++) {  // 8 iters
                int f = tid + it * 256;
                int c = f >> 4, d4 = f & 15;
                Bs4[c * B_STRIDE4 + d4] =
                    ((const float4*)cb)[((long)(kt * TC + c)) * (DDIM / 4) + (dc >> 2) + d4];
            }
            __syncthreads();

            int abase = dc >> 2;
#pragma unroll
            for (int d4 = 0; d4 < DCH / 4; d4++) {
                float4 a4[8], b4[8];
#pragma unroll
                for (int i = 0; i < 8; i++)
                    a4[i] = As4[(ty + 16 * i) * A_STRIDE4 + abase + d4];
#pragma unroll
                for (int j = 0; j < 8; j++)
                    b4[j] = Bs4[(tx + 16 * j) * B_STRIDE4 + d4];
#pragma unroll
                for (int i = 0; i < 8; i++)
#pragma unroll
                    for (int j = 0; j < 8; j++) {
                        acc[i][j] = fmaf(a4[i].x, b4[j].x, acc[i][j]);
                        acc[i][j] = fmaf(a4[i].y, b4[j].y, acc[i][j]);
                        acc[i][j] = fmaf(a4[i].z, b4[j].z, acc[i][j]);
                        acc[i][j] = fmaf(a4[i].w, b4[j].w, acc[i][j]);
                    }
            }
        }

        // epilogue: score = ||c||^2 - 2*dot, running argmin (ascending code
        // order + strict < implements first-occurrence tie-break)
#pragma unroll
        for (int j = 0; j < 8; j++) {
            int code = kt * TC + tx + 16 * j;
            float cn = __ldg(&g_cnorm[code]);
#pragma unroll
            for (int i = 0; i < 8; i++) {
                float s = fmaf(-2.f, acc[i][j], cn);
                if (s < rmin[i]) { rmin[i] = s; ridx[i] = code; }
            }
        }
    }

    // cross-thread (tx) reduction, packed (key|idx) u64 min, lowest idx on tie
    __syncthreads();
    unsigned long long* red = (unsigned long long*)sm4;
    unsigned long long mine[8];
#pragma unroll
    for (int i = 0; i < 8; i++)
        mine[i] = (((unsigned long long)fkey(rmin[i])) << 32) | (unsigned)ridx[i];
    if (tx == 0) {
#pragma unroll
        for (int i = 0; i < 8; i++) red[ty + 16 * i] = mine[i];
    }
    __syncthreads();
    for (int r = 1; r < 16; r++) {
        if (tx == r) {
#pragma unroll
            for (int i = 0; i < 8; i++) {
                int t = ty + 16 * i;
                if (mine[i] < red[t]) red[t] = mine[i];
            }
        }
        __syncthreads();
    }
    if (tid < TM) {
        g_idx[t0 + tid] = (int)(red[tid] & 0xffffffffu);
    }
}

// ---------------- gather z_q + per-token loss partial ----------------
__global__ void k_gather(const float* __restrict__ z, const float* __restrict__ cb,
                         float* __restrict__ out_zq, float* __restrict__ out_idx,
                         int has_idx) {
    int t = blockIdx.x;
    int d4 = threadIdx.x;   // 64 threads, 1 float4 each
    int idx = g_idx[t];
    float4 cv = ((const float4*)cb)[(long)idx * (DDIM / 4) + d4];
    float4 zv = ((const float4*)z)[(long)t * (DDIM / 4) + d4];
    ((float4*)out_zq)[(long)t * (DDIM / 4) + d4] = cv;   // z_q_ste value == z_q

    float dx = cv.x - zv.x, dy = cv.y - zv.y, dz = cv.z - zv.z, dw = cv.w - zv.w;
    float s = dx * dx + dy * dy + dz * dz + dw * dw;
#pragma unroll
    for (int o = 16; o; o >>= 1) s += __shfl_xor_sync(0xffffffffu, s, o);

    __shared__ float w0;
    if (threadIdx.x == 0) w0 = s;
    __syncthreads();
    if (threadIdx.x == 32) g_part[t] = w0 + s;   // deterministic 2-warp combine
    if (has_idx && threadIdx.x == 0) out_idx[t] = (float)idx;
}

// ---------------- deterministic final loss reduction ----------------
__global__ void k_loss(float* __restrict__ out_loss, int N) {
    __shared__ double red[256];
    double s = 0.0;
    for (int i = threadIdx.x; i < N; i += 256) s += (double)g_part[i];  // fixed order
    red[threadIdx.x] = s;
    __syncthreads();
    for (int o = 128; o; o >>= 1) {
        if (threadIdx.x < o) red[threadIdx.x] += red[threadIdx.x + o];
        __syncthreads();
    }
    if (threadIdx.x == 0)
        *out_loss = (float)(1.25 * red[0] / ((double)N * DDIM));
}

// ---------------- launch ----------------
extern "C" void kernel_launch(void* const* d_in, const int* in_sizes, int n_in,
                              void* d_out, int out_size) {
    const float* z  = (const float*)d_in[0];
    const float* cb = (const float*)d_in[1];
    int N = in_sizes[0] / DDIM;
    int K = in_sizes[1] / DDIM;
    float* out = (float*)d_out;

    cudaFuncSetAttribute(k_argmin, cudaFuncAttributeMaxDynamicSharedMemorySize,
                         SMEM_BYTES);

    k_cnorm<<<(K + 7) / 8, 256>>>(cb, K);
    k_argmin<<<N / TM, 256, SMEM_BYTES>>>(z, cb, K);

    // defensive output-layout handling: [z_q | idx? | loss?]
    long zq_elems = (long)N * DDIM;
    int has_idx  = (out_size >= zq_elems + N);
    int has_loss = (out_size >= zq_elems + N + 1);
    float* out_idx = has_idx ? (out + zq_elems) : nullptr;

    k_gather<<<N, 64>>>(z, cb, out, out_idx, has_idx);
    if (has_loss) {
        k_loss<<<1, 256>>>(out + zq_elems + N, N);
    }
}

// round 3
// speedup vs baseline: 5.0415x; 5.0415x over previous
#include <cuda_runtime.h>
#include <cuda_fp16.h>
#include <cstdint>

// ============================================================
// VectorQuantizer on GB300 (baseline-PTX path, no tcgen05):
//   fp16 mma.sync GEMM + per-thread top-4 + exact fp32 rescore.
// ============================================================

#define DDIM 256
#define MAXN 32768
#define MAXK 8192

__device__ __half g_zh[(size_t)MAXN * DDIM];   // fp16 tokens
__device__ __half g_ch[(size_t)MAXK * DDIM];   // fp16 codebook
__device__ float  g_cnorm[MAXK];
__device__ int    g_cand[(size_t)MAXN * 4];    // top-4 candidates per token
__device__ float  g_part[MAXN];                // per-token loss partial

// ---------------- PTX helpers ----------------
__device__ __forceinline__ uint32_t smem_u32(const void* p) {
    uint32_t a;
    asm("{ .reg .u64 t; cvta.to.shared.u64 t, %1; cvt.u32.u64 %0, t; }" : "=r"(a) : "l"(p));
    return a;
}
__device__ __forceinline__ void cp16(uint32_t s, const void* g) {
    asm volatile("cp.async.cg.shared.global [%0], [%1], 16;" :: "r"(s), "l"(g) : "memory");
}
__device__ __forceinline__ void cp_commit() {
    asm volatile("cp.async.commit_group;" ::: "memory");
}
template <int N> __device__ __forceinline__ void cp_wait() {
    asm volatile("cp.async.wait_group %0;" :: "n"(N) : "memory");
}
__device__ __forceinline__ void ldsm4(uint32_t a[4], uint32_t addr) {
    asm volatile("ldmatrix.sync.aligned.m8n8.x4.shared.b16 {%0,%1,%2,%3}, [%4];"
                 : "=r"(a[0]), "=r"(a[1]), "=r"(a[2]), "=r"(a[3]) : "r"(addr));
}
__device__ __forceinline__ void ldsm2(uint32_t b[2], uint32_t addr) {
    asm volatile("ldmatrix.sync.aligned.m8n8.x2.shared.b16 {%0,%1}, [%2];"
                 : "=r"(b[0]), "=r"(b[1]) : "r"(addr));
}
__device__ __forceinline__ void mma16816(float d[4], const uint32_t a[4],
                                         const uint32_t b[2]) {
    asm volatile(
        "mma.sync.aligned.m16n8k16.row.col.f32.f16.f16.f32 "
        "{%0,%1,%2,%3},{%4,%5,%6,%7},{%8,%9},{%0,%1,%2,%3};"
        : "+f"(d[0]), "+f"(d[1]), "+f"(d[2]), "+f"(d[3])
        : "r"(a[0]), "r"(a[1]), "r"(a[2]), "r"(a[3]), "r"(b[0]), "r"(b[1]));
}

__device__ __forceinline__ unsigned fkey(float f) {
    unsigned u = __float_as_uint(f);
    return (u & 0x80000000u) ? ~u : (u | 0x80000000u);
}

// ---------------- SMEM map for k_argmin ----------------
// [cn: 32768][A panel: 128 x 528B = 67584][B: 2 x 18432]
#define AS 528                  // A row stride bytes (256 halfs + 8 pad)
#define BS 144                  // B row stride bytes (64 halfs + 8 pad)
#define CN_OFF 0
#define A_OFF 32768
#define B_OFF 100352
#define B_BYTES 18432
#define SMEM_TOTAL 137216

// ---------------- prep kernels ----------------
__global__ void k_prep_z(const float* __restrict__ z, int n4) {
    int i = blockIdx.x * blockDim.x + threadIdx.x;
    if (i >= n4) return;
    float4 v = ((const float4*)z)[i];
    __half2 a = __floats2half2_rn(v.x, v.y);
    __half2 b = __floats2half2_rn(v.z, v.w);
    uint2 o; o.x = *(uint32_t*)&a; o.y = *(uint32_t*)&b;
    ((uint2*)g_zh)[i] = o;
}

__global__ void k_prep_c(const float* __restrict__ cb, int K) {
    int warp = blockIdx.x * (blockDim.x >> 5) + (threadIdx.x >> 5);
    int lane = threadIdx.x & 31;
    if (warp >= K) return;
    float s = 0.f;
#pragma unroll
    for (int i = 0; i < 2; i++) {
        int e4 = lane + 32 * i;
        float4 v = ((const float4*)(cb + (size_t)warp * DDIM))[e4];
        s += v.x * v.x + v.y * v.y + v.z * v.z + v.w * v.w;
        __half2 a = __floats2half2_rn(v.x, v.y);
        __half2 b = __floats2half2_rn(v.z, v.w);
        uint2 o; o.x = *(uint32_t*)&a; o.y = *(uint32_t*)&b;
        ((uint2*)(g_ch + (size_t)warp * DDIM))[e4] = o;
    }
#pragma unroll
    for (int o = 16; o; o >>= 1) s += __shfl_xor_sync(0xffffffffu, s, o);
    if (lane == 0) g_cnorm[warp] = s;
}

// ---------------- fused fp16 GEMM + top-4 argmin ----------------
__global__ void __launch_bounds__(256, 1) k_argmin(int ntiles) {
    extern __shared__ char smem[];
    uint32_t sb = smem_u32(smem);
    int tid = threadIdx.x;
    int lane = tid & 31, wid = tid >> 5;
    int wm = wid >> 2;          // M group (0..1): rows wm*64..+64
    int wn = wid & 3;           // N group (0..3): cols wn*32..+32
    long t0 = (long)blockIdx.x * 128;

    // ---- async prologue: A panel + cn table + B chunk 0 ----
#pragma unroll
    for (int it = 0; it < 16; it++) {           // A: 128 x 32 chunks of 16B
        int f = tid + 256 * it;
        int row = f >> 5, c = f & 31;
        cp16(sb + A_OFF + row * AS + c * 16,
             g_zh + (t0 + row) * DDIM + c * 8);
    }
#pragma unroll
    for (int it = 0; it < 8; it++) {            // cn: 8192 floats = 2048 x 16B
        int f = tid + 256 * it;
        cp16(sb + CN_OFF + f * 16, g_cnorm + f * 4);
    }
#pragma unroll
    for (int it = 0; it < 4; it++) {            // B chunk q=0
        int f = tid + 256 * it;
        int row = f >> 3, c = f & 7;
        cp16(sb + B_OFF + row * BS + c * 16,
             g_ch + (size_t)row * DDIM + c * 8);
    }
    cp_commit();

    // ---- state ----
    float d[4][4][4];
    float ts[8][4];
    int   ti[8][4];
#pragma unroll
    for (int s = 0; s < 8; s++)
#pragma unroll
        for (int e = 0; e < 4; e++) { ts[s][e] = 3.4e38f; ti[s][e] = 0; }

    // ldmatrix lane-address components (constant per thread)
    int a_r = (lane & 7) + ((lane >> 3) & 1) * 8;   // row within 16-row frag
    int a_k = ((lane >> 4) & 1) * 8;                // k-half
    int b_r = lane & 7;                             // code row within 8
    int b_k = ((lane >> 3) & 1) * 8;                // k-half (lanes 16-31 ignored)

    int Q = ntiles * 4;
    for (int q = 0; q < Q; q++) {
        int buf = q & 1;
        if (q + 1 < Q) {
            int nq = q + 1;
            int nkt = nq >> 2, ndc = nq & 3;
            uint32_t bb = sb + B_OFF + (nq & 1) * B_BYTES;
#pragma unroll
            for (int it = 0; it < 4; it++) {
                int f = tid + 256 * it;
                int row = f >> 3, c = f & 7;
                cp16(bb + row * BS + c * 16,
                     g_ch + ((size_t)(nkt * 128 + row)) * DDIM + ndc * 64 + c * 8);
            }
            cp_commit();
            cp_wait<1>();
        } else {
            cp_wait<0>();
        }
        __syncthreads();

        int kt = q >> 2, dc = q & 3;
        if (dc == 0) {
#pragma unroll
            for (int mi = 0; mi < 4; mi++)
#pragma unroll
                for (int ni = 0; ni < 4; ni++)
#pragma unroll
                    for (int r = 0; r < 4; r++) d[mi][ni][r] = 0.f;
        }
        uint32_t Bb = sb + B_OFF + buf * B_BYTES;

#pragma unroll
        for (int k0 = 0; k0 < 64; k0 += 16) {
            uint32_t a[4][4], bf[4][2];
#pragma unroll
            for (int mi = 0; mi < 4; mi++)
                ldsm4(a[mi], sb + A_OFF + (wm * 64 + mi * 16 + a_r) * AS +
                             (dc * 64 + k0 + a_k) * 2);
#pragma unroll
            for (int ni = 0; ni < 4; ni++)
                ldsm2(bf[ni], Bb + (wn * 32 + ni * 8 + b_r) * BS + (k0 + b_k) * 2);
#pragma unroll
            for (int mi = 0; mi < 4; mi++)
#pragma unroll
                for (int ni = 0; ni < 4; ni++)
                    mma16816(d[mi][ni], a[mi], bf[ni]);
        }

        if (dc == 3) {
            // ---- per-tile scoring: score = cn - 2*dot, per-slot min, top-4 ----
            int cbase = kt * 128 + wn * 32 + 2 * (lane & 3);
            float2 cn2[4];
#pragma unroll
            for (int ni = 0; ni < 4; ni++)
                cn2[ni] = *(const float2*)(smem + CN_OFF + (cbase + ni * 8) * 4);
#pragma unroll
            for (int mi = 0; mi < 4; mi++)
#pragma unroll
                for (int h = 0; h < 2; h++) {
                    int slot = mi * 2 + h;
                    float bs = 3.4e38f; int bc = 0;
#pragma unroll
                    for (int ni = 0; ni < 4; ni++) {
                        float s0 = fmaf(-2.f, d[mi][ni][h * 2 + 0], cn2[ni].x);
                        float s1 = fmaf(-2.f, d[mi][ni][h * 2 + 1], cn2[ni].y);
                        int c0 = cbase + ni * 8, c1 = c0 + 1;
                        if (s0 < bs) { bs = s0; bc = c0; }
                        if (s1 < bs) { bs = s1; bc = c1; }
                    }
                    // top-4 insert
                    if (bs < ts[slot][3]) {
                        if (bs < ts[slot][2]) {
                            ts[slot][3] = ts[slot][2]; ti[slot][3] = ti[slot][2];
                            if (bs < ts[slot][1]) {
                                ts[slot][2] = ts[slot][1]; ti[slot][2] = ti[slot][1];
                                if (bs < ts[slot][0]) {
                                    ts[slot][1] = ts[slot][0]; ti[slot][1] = ti[slot][0];
                                    ts[slot][0] = bs; ti[slot][0] = bc;
                                } else { ts[slot][1] = bs; ti[slot][1] = bc; }
                            } else { ts[slot][2] = bs; ti[slot][2] = bc; }
                        } else { ts[slot][3] = bs; ti[slot][3] = bc; }
                    }
                }
        }
        __syncthreads();
    }

    // ---- merge 16 contributors x 4 entries per token -> top-4 ----
    unsigned long long* red = (unsigned long long*)(smem + A_OFF);
    int contrib = wn * 4 + (lane & 3);
#pragma unroll
    for (int mi = 0; mi < 4; mi++)
#pragma unroll
        for (int h = 0; h < 2; h++) {
            int slot = mi * 2 + h;
            int token = wm * 64 + mi * 16 + h * 8 + (lane >> 2);
#pragma unroll
            for (int e = 0; e < 4; e++)
                red[token * 64 + contrib * 4 + e] =
                    (((unsigned long long)fkey(ts[slot][e])) << 32) |
                    (unsigned)ti[slot][e];
        }
    __syncthreads();

    if (tid < 128) {
        unsigned long long b1 = ~0ull, b2 = ~0ull, b3 = ~0ull, b4 = ~0ull;
#pragma unroll 4
        for (int j = 0; j < 64; j++) {
            unsigned long long v = red[tid * 64 + j];
            if (v < b4) {
                if (v < b3) {
                    b4 = b3;
                    if (v < b2) { b3 = b2; if (v < b1) { b2 = b1; b1 = v; } else b2 = v; }
                    else b3 = v;
                } else b4 = v;
            }
        }
        long t = t0 + tid;
        g_cand[t * 4 + 0] = (int)(b1 & 0xffffffffu);
        g_cand[t * 4 + 1] = (int)(b2 & 0xffffffffu);
        g_cand[t * 4 + 2] = (int)(b3 & 0xffffffffu);
        g_cand[t * 4 + 3] = (int)(b4 & 0xffffffffu);
    }
}

// ---------------- exact rescore + gather + loss partial ----------------
__global__ void k_finish(const float* __restrict__ z, const float* __restrict__ cb,
                         float* __restrict__ out_zq, float* __restrict__ out_idx,
                         int has_idx, int N) {
    int warp = blockIdx.x * (blockDim.x >> 5) + (threadIdx.x >> 5);
    int lane = threadIdx.x & 31;
    if (warp >= N) return;
    long t = warp;

    float4 xv0 = ((const float4*)z)[t * 64 + lane];
    float4 xv1 = ((const float4*)z)[t * 64 + 32 + lane];

    float best_s = 3.4e38f;
    int best_i = 0x7fffffff;
#pragma unroll
    for (int r = 0; r < 4; r++) {
        int ci = g_cand[t * 4 + r];
        float4 c0 = __ldg(&((const float4*)cb)[(long)ci * 64 + lane]);
        float4 c1 = __ldg(&((const float4*)cb)[(long)ci * 64 + 32 + lane]);
        float dx, s = 0.f;
        dx = xv0.x - c0.x; s += dx * dx;  dx = xv0.y - c0.y; s += dx * dx;
        dx = xv0.z - c0.z; s += dx * dx;  dx = xv0.w - c0.w; s += dx * dx;
        dx = xv1.x - c1.x; s += dx * dx;  dx = xv1.y - c1.y; s += dx * dx;
        dx = xv1.z - c1.z; s += dx * dx;  dx = xv1.w - c1.w; s += dx * dx;
#pragma unroll
        for (int o = 16; o; o >>= 1) s += __shfl_xor_sync(0xffffffffu, s, o);
        if (s < best_s || (s == best_s && ci < best_i)) { best_s = s; best_i = ci; }
    }
    float4 c0 = __ldg(&((const float4*)cb)[(long)best_i * 64 + lane]);
    float4 c1 = __ldg(&((const float4*)cb)[(long)best_i * 64 + 32 + lane]);
    ((float4*)out_zq)[t * 64 + lane] = c0;
    ((float4*)out_zq)[t * 64 + 32 + lane] = c1;
    if (lane == 0) {
        g_part[t] = best_s;
        if (has_idx) out_idx[t] = (float)best_i;
    }
}

__global__ void k_loss(float* __restrict__ out_loss, int N) {
    __shared__ double red[1024];
    double s = 0.0;
    for (int i = threadIdx.x; i < N; i += 1024) s += (double)g_part[i];
    red[threadIdx.x] = s;
    __syncthreads();
    for (int o = 512; o; o >>= 1) {
        if (threadIdx.x < o) red[threadIdx.x] += red[threadIdx.x + o];
        __syncthreads();
    }
    if (threadIdx.x == 0)
        *out_loss = (float)(1.25 * red[0] / ((double)N * DDIM));
}

// ---------------- launch ----------------
extern "C" void kernel_launch(void* const* d_in, const int* in_sizes, int n_in,
                              void* d_out, int out_size) {
    const float* z  = (const float*)d_in[0];
    const float* cb = (const float*)d_in[1];
    int N = in_sizes[0] / DDIM;
    int K = in_sizes[1] / DDIM;
    float* out = (float*)d_out;

    cudaFuncSetAttribute(k_argmin, cudaFuncAttributeMaxDynamicSharedMemorySize,
                         SMEM_TOTAL);

    int n4 = N * (DDIM / 4);
    k_prep_z<<<(n4 + 255) / 256, 256>>>(z, n4);
    k_prep_c<<<(K + 7) / 8, 256>>>(cb, K);
    k_argmin<<<N / 128, 256, SMEM_TOTAL>>>(K / 128);

    long zq_elems = (long)N * DDIM;
    int has_idx  = (out_size >= zq_elems + N);
    int has_loss = (out_size >= zq_elems + N + 1);
    float* out_idx = has_idx ? (out + zq_elems) : nullptr;

    k_finish<<<(N + 7) / 8, 256>>>(z, cb, out, out_idx, has_idx, N);
    if (has_loss) k_loss<<<1, 1024>>>(out + zq_elems + N, N);
}